// round 10
// baseline (speedup 1.0000x reference)
#include <cuda_runtime.h>
#include <cstdint>

// DynamicMaskHead: per-match 3-layer pixel MLP (10->8 gelu ->8 gelu ->1).
// Packed fp32x2 FFMA2 (2 pixels/inst) — pinned at the RF-banking rt3 floor
// (3 distinct 64-bit operands -> 1 issue / 3 cyc -> fma pipe_active 2/3).
// Weights duplicated (w,w) in smem; gelu via tanh.approx (MUFU pipe);
// 0.5 of gelu folded into consumer weights. R10: TPB=256 (half the block
// prologues), pair-0 init fold.

typedef unsigned long long u64t;

#define TPB 256   // threads per block
#define NP  4     // pixel-pairs per thread (8 consecutive pixels/thread)

__device__ __forceinline__ u64t pack2(float lo, float hi) {
    u64t r; asm("mov.b64 %0, {%1, %2};" : "=l"(r) : "f"(lo), "f"(hi)); return r;
}
__device__ __forceinline__ void unpack2(u64t v, float& lo, float& hi) {
    asm("mov.b64 {%0, %1}, %2;" : "=f"(lo), "=f"(hi) : "l"(v));
}
__device__ __forceinline__ u64t fma2(u64t a, u64t b, u64t c) {
    u64t d; asm("fma.rn.f32x2 %0, %1, %2, %3;" : "=l"(d) : "l"(a), "l"(b), "l"(c));
    return d;
}
__device__ __forceinline__ u64t mul2(u64t a, u64t b) {
    u64t d; asm("mul.rn.f32x2 %0, %1, %2;" : "=l"(d) : "l"(a), "l"(b));
    return d;
}
__device__ __forceinline__ float tanh_hw(float x) {
    float r; asm("tanh.approx.f32 %0, %1;" : "=f"(r) : "f"(x)); return r;
}

// g(x) = x * (1 + tanh(0.7978845608*(x + 0.044715 x^3))) = 2*gelu(x).
// The consumer layer's weights carry the 0.5.
__device__ __forceinline__ u64t gelu2x(u64t x, u64t K0, u64t K1) {
    u64t t = mul2(x, x);          // rt2
    u64t s = fma2(K1, t, K0);     // rt3
    u64t u = mul2(x, s);          // rt2
    float ua, ub; unpack2(u, ua, ub);
    u64t T = pack2(tanh_hw(ua), tanh_hw(ub));
    return fma2(x, T, x);         // rt2 (x deduped)
}

__global__ void __launch_bounds__(TPB, 2)
dmh_kernel(const float* __restrict__ E,
           const float* __restrict__ theta,
           const float* __restrict__ centers,
           const int*   __restrict__ bidx,
           float*       __restrict__ out)
{
    __shared__ u64t sw[169];   // theta row, duplicated (w,w); w2/w3 pre-scaled 0.5

    const int m   = blockIdx.y;
    const int tid = threadIdx.x;

    for (int i = tid; i < 169; i += TPB) {
        float w = __ldg(&theta[m * 169 + i]);
        // scale w2 (88..151) and w3 (160..167) by 0.5; biases untouched
        if ((i >= 88 && i < 152) || (i >= 160 && i < 168)) w *= 0.5f;
        sw[i] = pack2(w, w);
    }
    __syncthreads();

    const int   b  = __ldg(&bidx[m]);
    const float cx = __ldg(&centers[2 * m + 0]);
    const float cy = __ldg(&centers[2 * m + 1]);
    const float* Eb = E + ((size_t)b << 19);   // b * 8 * 65536

    const u64t K0 = pack2(0.7978845608f, 0.7978845608f);
    const u64t K1 = pack2(0.03567740814f, 0.03567740814f);  // 0.044715*k0

    // Geometry: 8 consecutive pixels per thread (never cross a row).
    // pix0 = bx*2048 + tid*8 ; row = pix0>>8 (const per thread) -> fy hoisted.
    const int pix0 = (blockIdx.x << 11) + (tid << 3);

    // ---- per-thread: cb[o] = b[o] + w9[o]*fy + w8[o]*fx(pair0) ----
    // H[0][o] = cb[o] directly (pair-0 fold); pairs 1..3 add w8*dfx.
    u64t H[NP][8];
    {
        float fy  = fmaf((float)(pix0 >> 8), 1.0f / 256.0f, 0.5f / 256.0f) - cy;
        float fxb = fmaf((float)(pix0 & 255), 1.0f / 256.0f, 0.5f / 256.0f) - cx;
        u64t  X9  = pack2(fy, fy);
        u64t  X80 = pack2(fxb, fxb + 1.0f / 256.0f);
#pragma unroll
        for (int o = 0; o < 8; o++) {
            u64t c = fma2(sw[o * 10 + 9], X9, sw[80 + o]);
            H[0][o] = fma2(sw[o * 10 + 8], X80, c);
        }
#pragma unroll
        for (int k = 1; k < NP; k++) {
            float d = (float)(2 * k) * (1.0f / 256.0f);
            u64t  D = pack2(d, d);
#pragma unroll
            for (int o = 0; o < 8; o++)
                H[k][o] = fma2(sw[o * 10 + 8], D, H[0][o]);
        }
    }

    // ---- layer 1 E channels: float4-loaded, double-buffered ----
    float4 c0, c1, n0, n1;
    c0 = *reinterpret_cast<const float4*>(Eb + pix0);
    c1 = *reinterpret_cast<const float4*>(Eb + pix0 + 4);
#pragma unroll
    for (int i = 0; i < 8; i++) {
        if (i < 7) {
            const float* p = Eb + ((size_t)(i + 1) << 16) + pix0;
            n0 = *reinterpret_cast<const float4*>(p);
            n1 = *reinterpret_cast<const float4*>(p + 4);
        }
        u64t Xi[NP];
        Xi[0] = pack2(c0.x, c0.y);
        Xi[1] = pack2(c0.z, c0.w);
        Xi[2] = pack2(c1.x, c1.y);
        Xi[3] = pack2(c1.z, c1.w);
#pragma unroll
        for (int o = 0; o < 8; o++) {
            u64t w = sw[o * 10 + i];
#pragma unroll
            for (int k = 0; k < NP; k++) H[k][o] = fma2(w, Xi[k], H[k][o]);
        }
        c0 = n0; c1 = n1;
    }

#pragma unroll
    for (int k = 0; k < NP; k++)
#pragma unroll
        for (int o = 0; o < 8; o++) H[k][o] = gelu2x(H[k][o], K0, K1);

    // ---- fused layer2 -> gelu -> layer3 (one output channel at a time) ----
    u64t acc[NP];
#pragma unroll
    for (int k = 0; k < NP; k++) acc[k] = sw[168];   // b3

#pragma unroll
    for (int o = 0; o < 8; o++) {
        u64t g[NP];
        u64t bo = sw[152 + o];
        // i = 0 folded into init
        {
            u64t w = sw[88 + o * 8];
#pragma unroll
            for (int k = 0; k < NP; k++) g[k] = fma2(w, H[k][0], bo);
        }
#pragma unroll
        for (int i = 1; i < 8; i++) {
            u64t w = sw[88 + o * 8 + i];
#pragma unroll
            for (int k = 0; k < NP; k++) g[k] = fma2(w, H[k][i], g[k]);
        }
        u64t w3 = sw[160 + o];
#pragma unroll
        for (int k = 0; k < NP; k++)
            acc[k] = fma2(w3, gelu2x(g[k], K0, K1), acc[k]);
    }

    // ---- store (two float4) ----
    float* outm = out + ((size_t)m << 16);
    float a0, a1, a2, a3;
    unpack2(acc[0], a0, a1); unpack2(acc[1], a2, a3);
    *reinterpret_cast<float4*>(outm + pix0) = make_float4(a0, a1, a2, a3);
    unpack2(acc[2], a0, a1); unpack2(acc[3], a2, a3);
    *reinterpret_cast<float4*>(outm + pix0 + 4) = make_float4(a0, a1, a2, a3);
}

extern "C" void kernel_launch(void* const* d_in, const int* in_sizes, int n_in,
                              void* d_out, int out_size)
{
    const float* E       = (const float*)d_in[0];
    const float* theta   = (const float*)d_in[1];
    const float* centers = (const float*)d_in[2];
    const int*   bidx    = (const int*)d_in[3];

    // 2048 pixels/block -> 32 blocks/match, 256 matches
    dim3 grid(65536 / (TPB * NP * 2), 256, 1);
    dmh_kernel<<<grid, TPB>>>(E, theta, centers, bidx, (float*)d_out);
}

// round 11
// speedup vs baseline: 1.0773x; 1.0773x over previous
#include <cuda_runtime.h>
#include <cstdint>

// DynamicMaskHead: per-match 3-layer pixel MLP (10->8 gelu ->8 gelu ->1).
// Packed fp32x2 FFMA2 (2 pixels/inst) — pinned at the RF-banking rt3 floor
// (3 distinct 64-bit operands -> 1 issue / 3 cyc -> fma pipe_active 2/3).
// Weights duplicated (w,w) in smem; gelu via tanh.approx (MUFU pipe);
// 0.5 of gelu folded into consumer weights.
// R11 = R9 (best, 133.4us) + pair-0 init fold. TPB kept at 128 — R10 showed
// wider CTAs regress via barrier coupling.

typedef unsigned long long u64t;

#define TPB 128   // threads per block
#define NP  4     // pixel-pairs per thread (8 consecutive pixels/thread)

__device__ __forceinline__ u64t pack2(float lo, float hi) {
    u64t r; asm("mov.b64 %0, {%1, %2};" : "=l"(r) : "f"(lo), "f"(hi)); return r;
}
__device__ __forceinline__ void unpack2(u64t v, float& lo, float& hi) {
    asm("mov.b64 {%0, %1}, %2;" : "=f"(lo), "=f"(hi) : "l"(v));
}
__device__ __forceinline__ u64t fma2(u64t a, u64t b, u64t c) {
    u64t d; asm("fma.rn.f32x2 %0, %1, %2, %3;" : "=l"(d) : "l"(a), "l"(b), "l"(c));
    return d;
}
__device__ __forceinline__ u64t mul2(u64t a, u64t b) {
    u64t d; asm("mul.rn.f32x2 %0, %1, %2;" : "=l"(d) : "l"(a), "l"(b));
    return d;
}
__device__ __forceinline__ float tanh_hw(float x) {
    float r; asm("tanh.approx.f32 %0, %1;" : "=f"(r) : "f"(x)); return r;
}

// g(x) = x * (1 + tanh(0.7978845608*(x + 0.044715 x^3))) = 2*gelu(x).
// The consumer layer's weights carry the 0.5.
__device__ __forceinline__ u64t gelu2x(u64t x, u64t K0, u64t K1) {
    u64t t = mul2(x, x);          // rt2
    u64t s = fma2(K1, t, K0);     // rt3
    u64t u = mul2(x, s);          // rt2
    float ua, ub; unpack2(u, ua, ub);
    u64t T = pack2(tanh_hw(ua), tanh_hw(ub));
    return fma2(x, T, x);         // rt2 (x deduped)
}

__global__ void __launch_bounds__(TPB, 4)
dmh_kernel(const float* __restrict__ E,
           const float* __restrict__ theta,
           const float* __restrict__ centers,
           const int*   __restrict__ bidx,
           float*       __restrict__ out)
{
    __shared__ u64t sw[169];   // theta row, duplicated (w,w); w2/w3 pre-scaled 0.5

    const int m   = blockIdx.y;
    const int tid = threadIdx.x;

    for (int i = tid; i < 169; i += TPB) {
        float w = __ldg(&theta[m * 169 + i]);
        // scale w2 (88..151) and w3 (160..167) by 0.5; biases untouched
        if ((i >= 88 && i < 152) || (i >= 160 && i < 168)) w *= 0.5f;
        sw[i] = pack2(w, w);
    }
    __syncthreads();

    const int   b  = __ldg(&bidx[m]);
    const float cx = __ldg(&centers[2 * m + 0]);
    const float cy = __ldg(&centers[2 * m + 1]);
    const float* Eb = E + ((size_t)b << 19);   // b * 8 * 65536

    const u64t K0 = pack2(0.7978845608f, 0.7978845608f);
    const u64t K1 = pack2(0.03567740814f, 0.03567740814f);  // 0.044715*k0

    // Geometry: 8 consecutive pixels per thread (never cross a row).
    // pix0 = bx*1024 + tid*8 ; row = pix0>>8 (const per thread) -> fy hoisted.
    const int pix0 = (blockIdx.x << 10) + (tid << 3);

    // ---- init: H[0][o] = b[o] + w9[o]*fy + w8[o]*fx0 (pair-0 fold);
    //      pairs 1..3: H[k][o] = H[0][o] + w8[o]*dfx(k) ----
    u64t H[NP][8];
    {
        float fy  = fmaf((float)(pix0 >> 8), 1.0f / 256.0f, 0.5f / 256.0f) - cy;
        float fxb = fmaf((float)(pix0 & 255), 1.0f / 256.0f, 0.5f / 256.0f) - cx;
        u64t  X9  = pack2(fy, fy);
        u64t  X80 = pack2(fxb, fxb + 1.0f / 256.0f);
#pragma unroll
        for (int o = 0; o < 8; o++) {
            u64t c = fma2(sw[o * 10 + 9], X9, sw[80 + o]);
            H[0][o] = fma2(sw[o * 10 + 8], X80, c);
        }
#pragma unroll
        for (int k = 1; k < NP; k++) {
            float d = (float)(2 * k) * (1.0f / 256.0f);
            u64t  D = pack2(d, d);
#pragma unroll
            for (int o = 0; o < 8; o++)
                H[k][o] = fma2(sw[o * 10 + 8], D, H[0][o]);
        }
    }

    // ---- layer 1 E channels: float4-loaded, double-buffered ----
    float4 c0, c1, n0, n1;
    c0 = *reinterpret_cast<const float4*>(Eb + pix0);
    c1 = *reinterpret_cast<const float4*>(Eb + pix0 + 4);
#pragma unroll
    for (int i = 0; i < 8; i++) {
        if (i < 7) {
            const float* p = Eb + ((size_t)(i + 1) << 16) + pix0;
            n0 = *reinterpret_cast<const float4*>(p);
            n1 = *reinterpret_cast<const float4*>(p + 4);
        }
        u64t Xi[NP];
        Xi[0] = pack2(c0.x, c0.y);
        Xi[1] = pack2(c0.z, c0.w);
        Xi[2] = pack2(c1.x, c1.y);
        Xi[3] = pack2(c1.z, c1.w);
#pragma unroll
        for (int o = 0; o < 8; o++) {
            u64t w = sw[o * 10 + i];
#pragma unroll
            for (int k = 0; k < NP; k++) H[k][o] = fma2(w, Xi[k], H[k][o]);
        }
        c0 = n0; c1 = n1;
    }

#pragma unroll
    for (int k = 0; k < NP; k++)
#pragma unroll
        for (int o = 0; o < 8; o++) H[k][o] = gelu2x(H[k][o], K0, K1);

    // ---- fused layer2 -> gelu -> layer3 (one output channel at a time) ----
    u64t acc[NP];
#pragma unroll
    for (int k = 0; k < NP; k++) acc[k] = sw[168];   // b3

#pragma unroll
    for (int o = 0; o < 8; o++) {
        u64t g[NP];
        u64t bo = sw[152 + o];
        // i = 0 folded into init
        {
            u64t w = sw[88 + o * 8];
#pragma unroll
            for (int k = 0; k < NP; k++) g[k] = fma2(w, H[k][0], bo);
        }
#pragma unroll
        for (int i = 1; i < 8; i++) {
            u64t w = sw[88 + o * 8 + i];
#pragma unroll
            for (int k = 0; k < NP; k++) g[k] = fma2(w, H[k][i], g[k]);
        }
        u64t w3 = sw[160 + o];
#pragma unroll
        for (int k = 0; k < NP; k++)
            acc[k] = fma2(w3, gelu2x(g[k], K0, K1), acc[k]);
    }

    // ---- store (two float4) ----
    float* outm = out + ((size_t)m << 16);
    float a0, a1, a2, a3;
    unpack2(acc[0], a0, a1); unpack2(acc[1], a2, a3);
    *reinterpret_cast<float4*>(outm + pix0) = make_float4(a0, a1, a2, a3);
    unpack2(acc[2], a0, a1); unpack2(acc[3], a2, a3);
    *reinterpret_cast<float4*>(outm + pix0 + 4) = make_float4(a0, a1, a2, a3);
}

extern "C" void kernel_launch(void* const* d_in, const int* in_sizes, int n_in,
                              void* d_out, int out_size)
{
    const float* E       = (const float*)d_in[0];
    const float* theta   = (const float*)d_in[1];
    const float* centers = (const float*)d_in[2];
    const int*   bidx    = (const int*)d_in[3];

    // 1024 pixels/block -> 64 blocks/match, 256 matches
    dim3 grid(65536 / (TPB * NP * 2), 256, 1);
    dmh_kernel<<<grid, TPB>>>(E, theta, centers, bidx, (float*)d_out);
}